// round 8
// baseline (speedup 1.0000x reference)
#include <cuda_runtime.h>
#include <cuda_bf16.h>
#include <cstdint>

#define D_MODEL 1024
#define HEADS   16
#define DH      64
#define BATCH   4
#define SEQ     2048
#define NTOK    (BATCH * SEQ)   // 8192

// ---------------- scratch (device globals; no runtime alloc allowed) -------
__device__ __nv_bfloat16 g_xhi[(size_t)NTOK * D_MODEL];
__device__ __nv_bfloat16 g_xlo[(size_t)NTOK * D_MODEL];
__device__ __nv_bfloat16 g_qkvhi[(size_t)NTOK * 3 * D_MODEL]; // [8192,3072]
__device__ __nv_bfloat16 g_qkvlo[(size_t)NTOK * 3 * D_MODEL];
__device__ __nv_bfloat16 g_chi[(size_t)NTOK * D_MODEL];
__device__ __nv_bfloat16 g_clo[(size_t)NTOK * D_MODEL];
__device__ __nv_bfloat16 g_wqhi[(size_t)3 * D_MODEL * D_MODEL]; // Wqkv^T [3072,1024]
__device__ __nv_bfloat16 g_wqlo[(size_t)3 * D_MODEL * D_MODEL];
__device__ __nv_bfloat16 g_wphi[(size_t)D_MODEL * D_MODEL];     // Wproj^T
__device__ __nv_bfloat16 g_wplo[(size_t)D_MODEL * D_MODEL];

// ---------------------------------------------------------------------------
// Helpers (portable ISA only — .target sm_103 without 'a')
// ---------------------------------------------------------------------------
__device__ __forceinline__ uint32_t smem_u32(const void* p) {
    uint32_t a;
    asm("{ .reg .u64 t; cvta.to.shared.u64 t, %1; cvt.u32.u64 %0, t; }"
        : "=r"(a) : "l"(p));
    return a;
}
__device__ __forceinline__ void cp16(uint32_t saddr, const void* gaddr) {
    asm volatile("cp.async.cg.shared.global [%0], [%1], 16;"
        :: "r"(saddr), "l"(gaddr));
}
#define CP_COMMIT() asm volatile("cp.async.commit_group;")
#define CP_WAIT(n)  asm volatile("cp.async.wait_group %0;" :: "n"(n))

__device__ __forceinline__ void ldm4(uint32_t* r, uint32_t a) {
    asm volatile("ldmatrix.sync.aligned.m8n8.x4.shared.b16 {%0,%1,%2,%3}, [%4];"
        : "=r"(r[0]), "=r"(r[1]), "=r"(r[2]), "=r"(r[3]) : "r"(a));
}
__device__ __forceinline__ void ldm4t(uint32_t* r, uint32_t a) {
    asm volatile("ldmatrix.sync.aligned.m8n8.x4.trans.shared.b16 {%0,%1,%2,%3}, [%4];"
        : "=r"(r[0]), "=r"(r[1]), "=r"(r[2]), "=r"(r[3]) : "r"(a));
}
__device__ __forceinline__ void mma16816(float* c, const uint32_t* a, const uint32_t* b) {
    asm volatile(
        "mma.sync.aligned.m16n8k16.row.col.f32.bf16.bf16.f32 "
        "{%0,%1,%2,%3}, {%4,%5,%6,%7}, {%8,%9}, {%0,%1,%2,%3};"
        : "+f"(c[0]), "+f"(c[1]), "+f"(c[2]), "+f"(c[3])
        : "r"(a[0]), "r"(a[1]), "r"(a[2]), "r"(a[3]), "r"(b[0]), "r"(b[1]));
}
__device__ __forceinline__ uint32_t pkbf(__nv_bfloat16 a, __nv_bfloat16 b) {
    __nv_bfloat162 t = __halves2bfloat162(a, b);
    return *reinterpret_cast<uint32_t*>(&t);
}
__device__ __forceinline__ uint32_t pk_hi2(float a, float b) {
    return pkbf(__float2bfloat16(a), __float2bfloat16(b));
}
__device__ __forceinline__ uint32_t pk_lo2(float a, float b) {
    __nv_bfloat16 ha = __float2bfloat16(a), hb = __float2bfloat16(b);
    return pkbf(__float2bfloat16(a - __bfloat162float(ha)),
                __float2bfloat16(b - __bfloat162float(hb)));
}

// swizzled offset in a 32-col bf16 tile (64B rows, 4 chunks)
__device__ __forceinline__ uint32_t gswz(int row, int chunk) {
    return (uint32_t)row * 64 + ((chunk ^ ((row >> 1) & 3)) << 4);
}
// swizzled offset in a 64-col bf16 tile (128B rows, 8 chunks)
__device__ __forceinline__ uint32_t aswz(int row, int chunk) {
    return (uint32_t)row * 128 + ((chunk ^ (row & 7)) << 4);
}

// ---------------------------------------------------------------------------
// Conversion kernels
// ---------------------------------------------------------------------------
__global__ __launch_bounds__(256) void convert_hilo(
    const float4* __restrict__ in, uint2* __restrict__ hi, uint2* __restrict__ lo, int n4)
{
    int i = blockIdx.x * 256 + threadIdx.x;
    if (i >= n4) return;
    float4 v = in[i];
    hi[i] = make_uint2(pk_hi2(v.x, v.y), pk_hi2(v.z, v.w));
    lo[i] = make_uint2(pk_lo2(v.x, v.y), pk_lo2(v.z, v.w));
}

__global__ __launch_bounds__(256) void transpose_hilo(
    const float* __restrict__ W, int K, int N,
    __nv_bfloat16* __restrict__ Thi, __nv_bfloat16* __restrict__ Tlo)
{
    __shared__ float tile[32][33];
    int kb = blockIdx.y * 32, nb = blockIdx.x * 32;
    int tx = threadIdx.x, ty = threadIdx.y;
#pragma unroll
    for (int i = 0; i < 32; i += 8)
        tile[ty + i][tx] = W[(size_t)(kb + ty + i) * N + nb + tx];
    __syncthreads();
#pragma unroll
    for (int i = 0; i < 32; i += 8) {
        int n = nb + ty + i, k = kb + tx;
        float v = tile[tx][ty + i];
        __nv_bfloat16 h = __float2bfloat16(v);
        Thi[(size_t)n * K + k] = h;
        Tlo[(size_t)n * K + k] = __float2bfloat16(v - __bfloat162float(h));
    }
}

// ---------------------------------------------------------------------------
// HMMA bf16x3 GEMM: C = (Ahi+Alo)[M,K] @ (Bhi+Blo)[N,K]^T + bias
// 128x128 CTA tile, K-chunk 32, swizzled 64B rows, 3-stage, 1 sync/iter.
// (unchanged from round 7 — measured win: 382us, tensor 67%)
// ---------------------------------------------------------------------------
#define TILEB    8192
#define STAGEB   (4 * TILEB)
#define NSTAGE   3
#define GEMM_SMEM (NSTAGE * STAGEB)  // 98304

__global__ __launch_bounds__(256, 2) void gemm_mma_bf16x3(
    int M, int N, int K,
    const __nv_bfloat16* __restrict__ Ahi, const __nv_bfloat16* __restrict__ Alo,
    const __nv_bfloat16* __restrict__ Bhi, const __nv_bfloat16* __restrict__ Blo,
    const float* __restrict__ bias,
    float* __restrict__ C,
    __nv_bfloat16* __restrict__ Chi, __nv_bfloat16* __restrict__ Clo,
    int hilo_out)
{
    extern __shared__ char smem[];
    const uint32_t sb = smem_u32(smem);

    const int tid = threadIdx.x;
    const int lane = tid & 31;
    const int wid = tid >> 5;
    const int warpM = wid & 3;
    const int warpN = wid >> 2;

    const size_t arow0 = (size_t)blockIdx.y * 128 * K;
    const size_t brow0 = (size_t)blockIdx.x * 128 * K;

    const int ldRow = tid >> 2;
    const int ldCh  = tid & 3;

    float acc[2][8][4] = {};
    const int NCH = K / 32;

    auto issue = [&](int c, int s) {
        const int k0 = c * 32;
        const uint32_t st = sb + s * STAGEB;
#pragma unroll
        for (int p = 0; p < 2; p++) {
            const int row = ldRow + p * 64;
            const uint32_t soff = gswz(row, ldCh);
            const size_t goff = (size_t)row * K + k0 + ldCh * 8;
            cp16(st + 0 * TILEB + soff, Ahi + arow0 + goff);
            cp16(st + 1 * TILEB + soff, Alo + arow0 + goff);
            cp16(st + 2 * TILEB + soff, Bhi + brow0 + goff);
            cp16(st + 3 * TILEB + soff, Blo + brow0 + goff);
        }
    };

    issue(0, 0); CP_COMMIT();
    issue(1, 1); CP_COMMIT();

    for (int c = 0; c < NCH; c++) {
        if (c + 1 < NCH) CP_WAIT(1);
        else CP_WAIT(0);
        __syncthreads();
        if (c + 2 < NCH) { issue(c + 2, (c + 2) % NSTAGE); CP_COMMIT(); }

        const uint32_t st  = sb + (c % NSTAGE) * STAGEB;
        const uint32_t sAh = st;
        const uint32_t sAl = st + TILEB;
        const uint32_t sBh = st + 2 * TILEB;
        const uint32_t sBl = st + 3 * TILEB;

#pragma unroll
        for (int ks = 0; ks < 2; ks++) {
            uint32_t ahi[2][4], alo[2][4];
            const int aRow = warpM * 32 + (lane & 15);
            const int aCh  = ks * 2 + (lane >> 4);
#pragma unroll
            for (int mt = 0; mt < 2; mt++) {
                const uint32_t off = gswz(aRow + mt * 16, aCh);
                ldm4(ahi[mt], sAh + off);
                ldm4(alo[mt], sAl + off);
            }
            uint32_t bhi[4][4], blo[4][4];
            const int bRow = warpN * 64 + ((lane >> 4) << 3) + (lane & 7);
            const int bCh  = ks * 2 + ((lane >> 3) & 1);
#pragma unroll
            for (int ntp = 0; ntp < 4; ntp++) {
                const uint32_t off = gswz(bRow + ntp * 16, bCh);
                ldm4(bhi[ntp], sBh + off);
                ldm4(blo[ntp], sBl + off);
            }
#pragma unroll
            for (int mt = 0; mt < 2; mt++) {
#pragma unroll
                for (int nt = 0; nt < 8; nt++) {
                    const uint32_t* bh = &bhi[nt >> 1][(nt & 1) * 2];
                    const uint32_t* bl = &blo[nt >> 1][(nt & 1) * 2];
                    mma16816(acc[mt][nt], ahi[mt], bh);
                    mma16816(acc[mt][nt], ahi[mt], bl);
                    mma16816(acc[mt][nt], alo[mt], bh);
                }
            }
        }
    }

    const int rBase = blockIdx.y * 128 + warpM * 32 + (lane >> 2);
    const int cBase = blockIdx.x * 128 + warpN * 64 + (lane & 3) * 2;
#pragma unroll
    for (int mt = 0; mt < 2; mt++) {
#pragma unroll
        for (int nt = 0; nt < 8; nt++) {
            const int gc = cBase + nt * 8;
            const float b0 = bias[gc], b1 = bias[gc + 1];
            const int r0 = rBase + mt * 16;
            float v00 = acc[mt][nt][0] + b0, v01 = acc[mt][nt][1] + b1;
            float v10 = acc[mt][nt][2] + b0, v11 = acc[mt][nt][3] + b1;
            if (!hilo_out) {
                *(float2*)(C + (size_t)r0 * N + gc) = make_float2(v00, v01);
                *(float2*)(C + (size_t)(r0 + 8) * N + gc) = make_float2(v10, v11);
            } else {
                *(uint32_t*)(Chi + (size_t)r0 * N + gc) = pk_hi2(v00, v01);
                *(uint32_t*)(Clo + (size_t)r0 * N + gc) = pk_lo2(v00, v01);
                *(uint32_t*)(Chi + (size_t)(r0 + 8) * N + gc) = pk_hi2(v10, v11);
                *(uint32_t*)(Clo + (size_t)(r0 + 8) * N + gc) = pk_lo2(v10, v11);
            }
        }
    }
}

// ---------------------------------------------------------------------------
// HMMA flash attention (bf16x3). Q fragments live in registers for the whole
// kernel; all 98304B smem = 3 KV stages (prefetch distance 2). 2 CTAs/SM.
// CTA: 128 queries of one (b,h); 8 warps x 16 rows. KV tile 64.
// ---------------------------------------------------------------------------
#define AKVT     8192
#define ASTAGEB  (4 * AKVT)              // Kh,Kl,Vh,Vl = 32768
#define ANST     3
#define ATT_SMEM (ANST * ASTAGEB)        // 98304

__global__ __launch_bounds__(256, 2) void attn_mma(
    const __nv_bfloat16* __restrict__ qkvhi,
    const __nv_bfloat16* __restrict__ qkvlo,
    __nv_bfloat16* __restrict__ chi,
    __nv_bfloat16* __restrict__ clo)
{
    extern __shared__ char smem[];
    const uint32_t sb = smem_u32(smem);

    const int tid = threadIdx.x;
    const int lane = tid & 31;
    const int wid = tid >> 5;

    const int b = blockIdx.y >> 4;
    const int h = blockIdx.y & 15;
    const int q0 = blockIdx.x * 128;
    const size_t row0 = (size_t)b * SEQ;

    const size_t qoff = (row0 + q0) * 3072 + h * 64;
    const size_t koff = row0 * 3072 + 1024 + h * 64;
    const size_t voff = row0 * 3072 + 2048 + h * 64;

    // ---- prologue: stage Q through smem once, hoist fragments to registers
    uint32_t qh[4][4], ql[4][4];
    {
#pragma unroll
        for (int i = 0; i < 4; i++) {
            int idx = tid + i * 256;
            int row = idx >> 3, ch = idx & 7;
            uint32_t so = aswz(row, ch);
            size_t go = (size_t)row * 3072 + ch * 8;
            cp16(sb + so, qkvhi + qoff + go);           // Q hi -> [0, 16384)
            cp16(sb + 16384 + so, qkvlo + qoff + go);   // Q lo -> [16384, 32768)
        }
        CP_COMMIT();
        CP_WAIT(0);
        __syncthreads();
        const int aRow = wid * 16 + (lane & 15);
#pragma unroll
        for (int ks = 0; ks < 4; ks++) {
            uint32_t off = aswz(aRow, ks * 2 + (lane >> 4));
            ldm4(qh[ks], sb + off);
            ldm4(ql[ks], sb + 16384 + off);
        }
        __syncthreads();   // everyone done reading Q before KV overwrites
    }

    auto issueKV = [&](int t, int s) {
        const uint32_t st = sb + s * ASTAGEB;
        const size_t kvrow = (size_t)t * 64;
#pragma unroll
        for (int i = 0; i < 2; i++) {
            int idx = tid + i * 256;
            int row = idx >> 3, ch = idx & 7;
            uint32_t so = aswz(row, ch);
            size_t go = (kvrow + row) * 3072 + ch * 8;
            cp16(st + 0 * AKVT + so, qkvhi + koff + go);
            cp16(st + 1 * AKVT + so, qkvlo + koff + go);
            cp16(st + 2 * AKVT + so, qkvhi + voff + go);
            cp16(st + 3 * AKVT + so, qkvlo + voff + go);
        }
    };
    issueKV(0, 0); CP_COMMIT();
    issueKV(1, 1); CP_COMMIT();

    float o[8][4] = {};
    float mA = -1e30f, mB = -1e30f, lA = 0.f, lB = 0.f;

    const int bRow0 = ((lane >> 4) << 3) + (lane & 7);
    const int bChSel = (lane >> 3) & 1;

    const int NT = SEQ / 64;
    for (int t = 0; t < NT; t++) {
        if (t + 1 < NT) CP_WAIT(1);
        else CP_WAIT(0);
        __syncthreads();
        if (t + 2 < NT) { issueKV(t + 2, (t + 2) % ANST); CP_COMMIT(); }

        const uint32_t st  = sb + (t % ANST) * ASTAGEB;
        const uint32_t sKh = st;
        const uint32_t sKl = st + AKVT;
        const uint32_t sVh = st + 2 * AKVT;
        const uint32_t sVl = st + 3 * AKVT;

        // ---- S = Q K^T (bf16x3); Q from registers, K per-np
        float s[8][4] = {};
#pragma unroll
        for (int ks = 0; ks < 4; ks++) {
#pragma unroll
            for (int np = 0; np < 4; np++) {
                uint32_t kh4[4], kl4[4];
                uint32_t off = aswz(bRow0 + np * 16, ks * 2 + bChSel);
                ldm4(kh4, sKh + off);
                ldm4(kl4, sKl + off);
                mma16816(s[2 * np],     qh[ks], &kh4[0]);
                mma16816(s[2 * np],     qh[ks], &kl4[0]);
                mma16816(s[2 * np],     ql[ks], &kh4[0]);
                mma16816(s[2 * np + 1], qh[ks], &kh4[2]);
                mma16816(s[2 * np + 1], qh[ks], &kl4[2]);
                mma16816(s[2 * np + 1], ql[ks], &kh4[2]);
            }
        }

        // ---- online softmax
        float rmaxA = -1e30f, rmaxB = -1e30f;
#pragma unroll
        for (int nt = 0; nt < 8; nt++) {
#pragma unroll
            for (int j = 0; j < 4; j++) s[nt][j] *= 0.125f;
            rmaxA = fmaxf(rmaxA, fmaxf(s[nt][0], s[nt][1]));
            rmaxB = fmaxf(rmaxB, fmaxf(s[nt][2], s[nt][3]));
        }
        rmaxA = fmaxf(rmaxA, __shfl_xor_sync(0xffffffffu, rmaxA, 1));
        rmaxA = fmaxf(rmaxA, __shfl_xor_sync(0xffffffffu, rmaxA, 2));
        rmaxB = fmaxf(rmaxB, __shfl_xor_sync(0xffffffffu, rmaxB, 1));
        rmaxB = fmaxf(rmaxB, __shfl_xor_sync(0xffffffffu, rmaxB, 2));

        float mnA = fmaxf(mA, rmaxA), mnB = fmaxf(mB, rmaxB);
        float corrA = __expf(mA - mnA), corrB = __expf(mB - mnB);
        mA = mnA; mB = mnB;

        float rsA = 0.f, rsB = 0.f;
#pragma unroll
        for (int nt = 0; nt < 8; nt++) {
            s[nt][0] = __expf(s[nt][0] - mnA);
            s[nt][1] = __expf(s[nt][1] - mnA);
            s[nt][2] = __expf(s[nt][2] - mnB);
            s[nt][3] = __expf(s[nt][3] - mnB);
            rsA += s[nt][0] + s[nt][1];
            rsB += s[nt][2] + s[nt][3];
        }
        rsA += __shfl_xor_sync(0xffffffffu, rsA, 1);
        rsA += __shfl_xor_sync(0xffffffffu, rsA, 2);
        rsB += __shfl_xor_sync(0xffffffffu, rsB, 1);
        rsB += __shfl_xor_sync(0xffffffffu, rsB, 2);
        lA = lA * corrA + rsA;
        lB = lB * corrB + rsB;
#pragma unroll
        for (int nt = 0; nt < 8; nt++) {
            o[nt][0] *= corrA; o[nt][1] *= corrA;
            o[nt][2] *= corrB; o[nt][3] *= corrB;
        }

        // ---- O += P V (P hi/lo from registers, V per-np via ldmatrix.trans)
#pragma unroll
        for (int t4 = 0; t4 < 4; t4++) {
            uint32_t ph[4], pl[4];
            {
                const float* s0 = s[2 * t4];
                const float* s1 = s[2 * t4 + 1];
                ph[0] = pk_hi2(s0[0], s0[1]);  pl[0] = pk_lo2(s0[0], s0[1]);
                ph[1] = pk_hi2(s0[2], s0[3]);  pl[1] = pk_lo2(s0[2], s0[3]);
                ph[2] = pk_hi2(s1[0], s1[1]);  pl[2] = pk_lo2(s1[0], s1[1]);
                ph[3] = pk_hi2(s1[2], s1[3]);  pl[3] = pk_lo2(s1[2], s1[3]);
            }
            const int vRow = t4 * 16 + (lane & 15);
#pragma unroll
            for (int np = 0; np < 4; np++) {
                uint32_t vh[4], vl[4];
                uint32_t off = aswz(vRow, np * 2 + (lane >> 4));
                ldm4t(vh, sVh + off);
                ldm4t(vl, sVl + off);
                mma16816(o[2 * np],     ph, &vh[0]);
                mma16816(o[2 * np],     ph, &vl[0]);
                mma16816(o[2 * np],     pl, &vh[0]);
                mma16816(o[2 * np + 1], ph, &vh[2]);
                mma16816(o[2 * np + 1], ph, &vl[2]);
                mma16816(o[2 * np + 1], pl, &vh[2]);
            }
        }
    }

    // ---- epilogue: normalize, split hi/lo, store ctx
    const float ivA = 1.f / lA, ivB = 1.f / lB;
    const size_t tokA = row0 + q0 + wid * 16 + (lane >> 2);
    const size_t tokB = tokA + 8;
#pragma unroll
    for (int nt = 0; nt < 8; nt++) {
        const int col = h * 64 + nt * 8 + (lane & 3) * 2;
        float v0 = o[nt][0] * ivA, v1 = o[nt][1] * ivA;
        float v2 = o[nt][2] * ivB, v3 = o[nt][3] * ivB;
        *(uint32_t*)(chi + tokA * D_MODEL + col) = pk_hi2(v0, v1);
        *(uint32_t*)(clo + tokA * D_MODEL + col) = pk_lo2(v0, v1);
        *(uint32_t*)(chi + tokB * D_MODEL + col) = pk_hi2(v2, v3);
        *(uint32_t*)(clo + tokB * D_MODEL + col) = pk_lo2(v2, v3);
    }
}

// ---------------------------------------------------------------------------
// Launch
// ---------------------------------------------------------------------------
extern "C" void kernel_launch(void* const* d_in, const int* in_sizes, int n_in,
                              void* d_out, int out_size)
{
    const float* x      = (const float*)d_in[0];
    const float* w_qkv  = (const float*)d_in[1];
    const float* b_qkv  = (const float*)d_in[2];
    const float* w_proj = (const float*)d_in[3];
    const float* b_proj = (const float*)d_in[4];
    float* out = (float*)d_out;

    __nv_bfloat16 *xhi, *xlo, *qkvhi, *qkvlo, *chi, *clo, *wqhi, *wqlo, *wphi, *wplo;
    cudaGetSymbolAddress((void**)&xhi, g_xhi);
    cudaGetSymbolAddress((void**)&xlo, g_xlo);
    cudaGetSymbolAddress((void**)&qkvhi, g_qkvhi);
    cudaGetSymbolAddress((void**)&qkvlo, g_qkvlo);
    cudaGetSymbolAddress((void**)&chi, g_chi);
    cudaGetSymbolAddress((void**)&clo, g_clo);
    cudaGetSymbolAddress((void**)&wqhi, g_wqhi);
    cudaGetSymbolAddress((void**)&wqlo, g_wqlo);
    cudaGetSymbolAddress((void**)&wphi, g_wphi);
    cudaGetSymbolAddress((void**)&wplo, g_wplo);

    cudaFuncSetAttribute(gemm_mma_bf16x3,
                         cudaFuncAttributeMaxDynamicSharedMemorySize, GEMM_SMEM);
    cudaFuncSetAttribute(attn_mma,
                         cudaFuncAttributeMaxDynamicSharedMemorySize, ATT_SMEM);

    // 1) x -> bf16 hi/lo; weights transpose+split
    {
        int n4 = NTOK * D_MODEL / 4;
        convert_hilo<<<(n4 + 255) / 256, 256>>>((const float4*)x, (uint2*)xhi, (uint2*)xlo, n4);
        dim3 tg(3 * D_MODEL / 32, D_MODEL / 32);
        transpose_hilo<<<tg, dim3(32, 8)>>>(w_qkv, D_MODEL, 3 * D_MODEL, wqhi, wqlo);
        dim3 tp(D_MODEL / 32, D_MODEL / 32);
        transpose_hilo<<<tp, dim3(32, 8)>>>(w_proj, D_MODEL, D_MODEL, wphi, wplo);
    }

    // 2) QKV GEMM -> bf16 hi/lo qkv
    {
        dim3 grid(3 * D_MODEL / 128, NTOK / 128);
        gemm_mma_bf16x3<<<grid, 256, GEMM_SMEM>>>(NTOK, 3 * D_MODEL, D_MODEL,
                                                  xhi, xlo, wqhi, wqlo, b_qkv,
                                                  nullptr, qkvhi, qkvlo, 1);
    }

    // 3) HMMA flash attention -> bf16 hi/lo ctx
    {
        dim3 grid(SEQ / 128, BATCH * HEADS);
        attn_mma<<<grid, 256, ATT_SMEM>>>(qkvhi, qkvlo, chi, clo);
    }

    // 4) Proj GEMM -> fp32 out
    {
        dim3 grid(D_MODEL / 128, NTOK / 128);
        gemm_mma_bf16x3<<<grid, 256, GEMM_SMEM>>>(NTOK, D_MODEL, D_MODEL,
                                                  chi, clo, wphi, wplo, b_proj,
                                                  out, nullptr, nullptr, 0);
    }
}

// round 9
// speedup vs baseline: 1.0437x; 1.0437x over previous
#include <cuda_runtime.h>
#include <cuda_bf16.h>
#include <cstdint>

#define D_MODEL 1024
#define HEADS   16
#define DH      64
#define BATCH   4
#define SEQ     2048
#define NTOK    (BATCH * SEQ)   // 8192

// Q pre-scale: 0.125 (dh^-1/2) * log2(e)  -> softmax done in base-2 domain
#define QSCALE 0.1803368801111204f

// ---------------- scratch (device globals; no runtime alloc allowed) -------
__device__ __nv_bfloat16 g_xhi[(size_t)NTOK * D_MODEL];
__device__ __nv_bfloat16 g_xlo[(size_t)NTOK * D_MODEL];
__device__ __nv_bfloat16 g_qkvhi[(size_t)NTOK * 3 * D_MODEL]; // [8192,3072]
__device__ __nv_bfloat16 g_qkvlo[(size_t)NTOK * 3 * D_MODEL];
__device__ __nv_bfloat16 g_chi[(size_t)NTOK * D_MODEL];
__device__ __nv_bfloat16 g_clo[(size_t)NTOK * D_MODEL];
__device__ __nv_bfloat16 g_wqhi[(size_t)3 * D_MODEL * D_MODEL]; // Wqkv^T [3072,1024]
__device__ __nv_bfloat16 g_wqlo[(size_t)3 * D_MODEL * D_MODEL];
__device__ __nv_bfloat16 g_wphi[(size_t)D_MODEL * D_MODEL];     // Wproj^T
__device__ __nv_bfloat16 g_wplo[(size_t)D_MODEL * D_MODEL];

// ---------------------------------------------------------------------------
// Helpers (portable ISA only — .target sm_103 without 'a')
// ---------------------------------------------------------------------------
__device__ __forceinline__ uint32_t smem_u32(const void* p) {
    uint32_t a;
    asm("{ .reg .u64 t; cvta.to.shared.u64 t, %1; cvt.u32.u64 %0, t; }"
        : "=r"(a) : "l"(p));
    return a;
}
__device__ __forceinline__ void cp16(uint32_t saddr, const void* gaddr) {
    asm volatile("cp.async.cg.shared.global [%0], [%1], 16;"
        :: "r"(saddr), "l"(gaddr));
}
#define CP_COMMIT() asm volatile("cp.async.commit_group;")
#define CP_WAIT(n)  asm volatile("cp.async.wait_group %0;" :: "n"(n))

__device__ __forceinline__ void ldm4(uint32_t* r, uint32_t a) {
    asm volatile("ldmatrix.sync.aligned.m8n8.x4.shared.b16 {%0,%1,%2,%3}, [%4];"
        : "=r"(r[0]), "=r"(r[1]), "=r"(r[2]), "=r"(r[3]) : "r"(a));
}
__device__ __forceinline__ void ldm4t(uint32_t* r, uint32_t a) {
    asm volatile("ldmatrix.sync.aligned.m8n8.x4.trans.shared.b16 {%0,%1,%2,%3}, [%4];"
        : "=r"(r[0]), "=r"(r[1]), "=r"(r[2]), "=r"(r[3]) : "r"(a));
}
__device__ __forceinline__ void mma16816(float* c, const uint32_t* a, const uint32_t* b) {
    asm volatile(
        "mma.sync.aligned.m16n8k16.row.col.f32.bf16.bf16.f32 "
        "{%0,%1,%2,%3}, {%4,%5,%6,%7}, {%8,%9}, {%0,%1,%2,%3};"
        : "+f"(c[0]), "+f"(c[1]), "+f"(c[2]), "+f"(c[3])
        : "r"(a[0]), "r"(a[1]), "r"(a[2]), "r"(a[3]), "r"(b[0]), "r"(b[1]));
}

// Fast hi/lo bf16x2 pack: 2x cvt.rn.bf16x2 + bitwise hi reconstruction.
// h = {bf16(a) lo-half, bf16(b) hi-half}; l = packed residuals.
__device__ __forceinline__ void pk_hilo2(float a, float b, uint32_t& h, uint32_t& l) {
    asm("cvt.rn.bf16x2.f32 %0, %1, %2;" : "=r"(h) : "f"(b), "f"(a));
    float ha = __uint_as_float(h << 16);
    float hb = __uint_as_float(h & 0xffff0000u);
    float la = a - ha;
    float lb = b - hb;
    asm("cvt.rn.bf16x2.f32 %0, %1, %2;" : "=r"(l) : "f"(lb), "f"(la));
}

// swizzled offset in a 32-col bf16 tile (64B rows, 4 chunks)
__device__ __forceinline__ uint32_t gswz(int row, int chunk) {
    return (uint32_t)row * 64 + ((chunk ^ ((row >> 1) & 3)) << 4);
}
// swizzled offset in a 64-col bf16 tile (128B rows, 8 chunks)
__device__ __forceinline__ uint32_t aswz(int row, int chunk) {
    return (uint32_t)row * 128 + ((chunk ^ (row & 7)) << 4);
}

// ---------------------------------------------------------------------------
// Conversion kernels
// ---------------------------------------------------------------------------
__global__ __launch_bounds__(256) void convert_hilo(
    const float4* __restrict__ in, uint2* __restrict__ hi, uint2* __restrict__ lo, int n4)
{
    int i = blockIdx.x * 256 + threadIdx.x;
    if (i >= n4) return;
    float4 v = in[i];
    uint2 h, l;
    pk_hilo2(v.x, v.y, h.x, l.x);
    pk_hilo2(v.z, v.w, h.y, l.y);
    hi[i] = h;
    lo[i] = l;
}

__global__ __launch_bounds__(256) void transpose_hilo(
    const float* __restrict__ W, int K, int N,
    __nv_bfloat16* __restrict__ Thi, __nv_bfloat16* __restrict__ Tlo)
{
    __shared__ float tile[32][33];
    int kb = blockIdx.y * 32, nb = blockIdx.x * 32;
    int tx = threadIdx.x, ty = threadIdx.y;
#pragma unroll
    for (int i = 0; i < 32; i += 8)
        tile[ty + i][tx] = W[(size_t)(kb + ty + i) * N + nb + tx];
    __syncthreads();
#pragma unroll
    for (int i = 0; i < 32; i += 8) {
        int n = nb + ty + i, k = kb + tx;
        float v = tile[tx][ty + i];
        __nv_bfloat16 h = __float2bfloat16(v);
        Thi[(size_t)n * K + k] = h;
        Tlo[(size_t)n * K + k] = __float2bfloat16(v - __bfloat162float(h));
    }
}

// ---------------------------------------------------------------------------
// HMMA bf16x3 GEMM: C = (Ahi+Alo)[M,K] @ (Bhi+Blo)[N,K]^T + bias
// 128x128 CTA tile, K-chunk 32, swizzled 64B rows, 3-stage, 1 sync/iter.
// hilo_out=1 additionally pre-scales columns < 1024 (the Q block) by QSCALE.
// ---------------------------------------------------------------------------
#define TILEB    8192
#define STAGEB   (4 * TILEB)
#define NSTAGE   3
#define GEMM_SMEM (NSTAGE * STAGEB)  // 98304

__global__ __launch_bounds__(256, 2) void gemm_mma_bf16x3(
    int M, int N, int K,
    const __nv_bfloat16* __restrict__ Ahi, const __nv_bfloat16* __restrict__ Alo,
    const __nv_bfloat16* __restrict__ Bhi, const __nv_bfloat16* __restrict__ Blo,
    const float* __restrict__ bias,
    float* __restrict__ C,
    __nv_bfloat16* __restrict__ Chi, __nv_bfloat16* __restrict__ Clo,
    int hilo_out)
{
    extern __shared__ char smem[];
    const uint32_t sb = smem_u32(smem);

    const int tid = threadIdx.x;
    const int lane = tid & 31;
    const int wid = tid >> 5;
    const int warpM = wid & 3;
    const int warpN = wid >> 2;

    const size_t arow0 = (size_t)blockIdx.y * 128 * K;
    const size_t brow0 = (size_t)blockIdx.x * 128 * K;

    const int ldRow = tid >> 2;
    const int ldCh  = tid & 3;

    float acc[2][8][4] = {};
    const int NCH = K / 32;

    auto issue = [&](int c, int s) {
        const int k0 = c * 32;
        const uint32_t st = sb + s * STAGEB;
#pragma unroll
        for (int p = 0; p < 2; p++) {
            const int row = ldRow + p * 64;
            const uint32_t soff = gswz(row, ldCh);
            const size_t goff = (size_t)row * K + k0 + ldCh * 8;
            cp16(st + 0 * TILEB + soff, Ahi + arow0 + goff);
            cp16(st + 1 * TILEB + soff, Alo + arow0 + goff);
            cp16(st + 2 * TILEB + soff, Bhi + brow0 + goff);
            cp16(st + 3 * TILEB + soff, Blo + brow0 + goff);
        }
    };

    issue(0, 0); CP_COMMIT();
    issue(1, 1); CP_COMMIT();

    for (int c = 0; c < NCH; c++) {
        if (c + 1 < NCH) CP_WAIT(1);
        else CP_WAIT(0);
        __syncthreads();
        if (c + 2 < NCH) { issue(c + 2, (c + 2) % NSTAGE); CP_COMMIT(); }

        const uint32_t st  = sb + (c % NSTAGE) * STAGEB;
        const uint32_t sAh = st;
        const uint32_t sAl = st + TILEB;
        const uint32_t sBh = st + 2 * TILEB;
        const uint32_t sBl = st + 3 * TILEB;

#pragma unroll
        for (int ks = 0; ks < 2; ks++) {
            uint32_t ahi[2][4], alo[2][4];
            const int aRow = warpM * 32 + (lane & 15);
            const int aCh  = ks * 2 + (lane >> 4);
#pragma unroll
            for (int mt = 0; mt < 2; mt++) {
                const uint32_t off = gswz(aRow + mt * 16, aCh);
                ldm4(ahi[mt], sAh + off);
                ldm4(alo[mt], sAl + off);
            }
            uint32_t bhi[4][4], blo[4][4];
            const int bRow = warpN * 64 + ((lane >> 4) << 3) + (lane & 7);
            const int bCh  = ks * 2 + ((lane >> 3) & 1);
#pragma unroll
            for (int ntp = 0; ntp < 4; ntp++) {
                const uint32_t off = gswz(bRow + ntp * 16, bCh);
                ldm4(bhi[ntp], sBh + off);
                ldm4(blo[ntp], sBl + off);
            }
#pragma unroll
            for (int mt = 0; mt < 2; mt++) {
#pragma unroll
                for (int nt = 0; nt < 8; nt++) {
                    const uint32_t* bh = &bhi[nt >> 1][(nt & 1) * 2];
                    const uint32_t* bl = &blo[nt >> 1][(nt & 1) * 2];
                    mma16816(acc[mt][nt], ahi[mt], bh);
                    mma16816(acc[mt][nt], ahi[mt], bl);
                    mma16816(acc[mt][nt], alo[mt], bh);
                }
            }
        }
    }

    const int rBase = blockIdx.y * 128 + warpM * 32 + (lane >> 2);
    const int cBase = blockIdx.x * 128 + warpN * 64 + (lane & 3) * 2;
#pragma unroll
    for (int mt = 0; mt < 2; mt++) {
#pragma unroll
        for (int nt = 0; nt < 8; nt++) {
            const int gc = cBase + nt * 8;
            const float b0 = bias[gc], b1 = bias[gc + 1];
            const int r0 = rBase + mt * 16;
            float v00 = acc[mt][nt][0] + b0, v01 = acc[mt][nt][1] + b1;
            float v10 = acc[mt][nt][2] + b0, v11 = acc[mt][nt][3] + b1;
            if (!hilo_out) {
                *(float2*)(C + (size_t)r0 * N + gc) = make_float2(v00, v01);
                *(float2*)(C + (size_t)(r0 + 8) * N + gc) = make_float2(v10, v11);
            } else {
                // Q block (cols < 1024) pre-scaled for log2-domain softmax
                const float qs = (gc < 1024) ? QSCALE : 1.0f;
                v00 *= qs; v01 *= qs; v10 *= qs; v11 *= qs;
                uint32_t h0, l0, h1, l1;
                pk_hilo2(v00, v01, h0, l0);
                pk_hilo2(v10, v11, h1, l1);
                *(uint32_t*)(Chi + (size_t)r0 * N + gc) = h0;
                *(uint32_t*)(Clo + (size_t)r0 * N + gc) = l0;
                *(uint32_t*)(Chi + (size_t)(r0 + 8) * N + gc) = h1;
                *(uint32_t*)(Clo + (size_t)(r0 + 8) * N + gc) = l1;
            }
        }
    }
}

// ---------------------------------------------------------------------------
// HMMA flash attention (bf16x3, log2-domain softmax). Round-7 structure:
// Q staged in smem, 2-stage KV, 128B swizzled rows, 98304B smem, 2 CTAs/SM.
// CTA: 128 queries of one (b,h); 8 warps x 16 rows. KV tile 64.
// ---------------------------------------------------------------------------
#define AQTILE   16384
#define AKVT     8192
#define ASTAGEB  (4 * AKVT)
#define ATT_SMEM (2 * AQTILE + 2 * ASTAGEB)  // 98304

__global__ __launch_bounds__(256, 2) void attn_mma(
    const __nv_bfloat16* __restrict__ qkvhi,
    const __nv_bfloat16* __restrict__ qkvlo,
    __nv_bfloat16* __restrict__ chi,
    __nv_bfloat16* __restrict__ clo)
{
    extern __shared__ char smem[];
    const uint32_t sb = smem_u32(smem);
    const uint32_t sQh = sb;
    const uint32_t sQl = sb + AQTILE;
    const uint32_t sKV = sb + 2 * AQTILE;

    const int tid = threadIdx.x;
    const int lane = tid & 31;
    const int wid = tid >> 5;

    const int b = blockIdx.y >> 4;
    const int h = blockIdx.y & 15;
    const int q0 = blockIdx.x * 128;
    const size_t row0 = (size_t)b * SEQ;

    const size_t qoff = (row0 + q0) * 3072 + h * 64;
    const size_t koff = row0 * 3072 + 1024 + h * 64;
    const size_t voff = row0 * 3072 + 2048 + h * 64;

#pragma unroll
    for (int i = 0; i < 4; i++) {
        int idx = tid + i * 256;
        int row = idx >> 3, ch = idx & 7;
        uint32_t so = aswz(row, ch);
        size_t go = (size_t)row * 3072 + ch * 8;
        cp16(sQh + so, qkvhi + qoff + go);
        cp16(sQl + so, qkvlo + qoff + go);
    }

    auto issueKV = [&](int t, int s) {
        const uint32_t st = sKV + s * ASTAGEB;
        const size_t kvrow = (size_t)t * 64;
#pragma unroll
        for (int i = 0; i < 2; i++) {
            int idx = tid + i * 256;
            int row = idx >> 3, ch = idx & 7;
            uint32_t so = aswz(row, ch);
            size_t go = (kvrow + row) * 3072 + ch * 8;
            cp16(st + 0 * AKVT + so, qkvhi + koff + go);
            cp16(st + 1 * AKVT + so, qkvlo + koff + go);
            cp16(st + 2 * AKVT + so, qkvhi + voff + go);
            cp16(st + 3 * AKVT + so, qkvlo + voff + go);
        }
    };
    issueKV(0, 0);
    CP_COMMIT();

    float o[8][4] = {};
    float mA = -1e30f, mB = -1e30f, lA = 0.f, lB = 0.f;

    const int bRow0 = ((lane >> 4) << 3) + (lane & 7);
    const int bChSel = (lane >> 3) & 1;

    const int NT = SEQ / 64;
    for (int t = 0; t < NT; t++) {
        CP_WAIT(0);
        __syncthreads();
        if (t + 1 < NT) { issueKV(t + 1, (t + 1) & 1); CP_COMMIT(); }

        const uint32_t st  = sKV + (t & 1) * ASTAGEB;
        const uint32_t sKh = st;
        const uint32_t sKl = st + AKVT;
        const uint32_t sVh = st + 2 * AKVT;
        const uint32_t sVl = st + 3 * AKVT;

        // ---- S = Q K^T (bf16x3); Q per-ks from smem, K per-np
        float s[8][4] = {};
        const int aRow = wid * 16 + (lane & 15);
#pragma unroll
        for (int ks = 0; ks < 4; ks++) {
            uint32_t qh4[4], ql4[4];
            {
                uint32_t off = aswz(aRow, ks * 2 + (lane >> 4));
                ldm4(qh4, sQh + off);
                ldm4(ql4, sQl + off);
            }
#pragma unroll
            for (int np = 0; np < 4; np++) {
                uint32_t kh4[4], kl4[4];
                uint32_t off = aswz(bRow0 + np * 16, ks * 2 + bChSel);
                ldm4(kh4, sKh + off);
                ldm4(kl4, sKl + off);
                mma16816(s[2 * np],     qh4, &kh4[0]);
                mma16816(s[2 * np],     qh4, &kl4[0]);
                mma16816(s[2 * np],     ql4, &kh4[0]);
                mma16816(s[2 * np + 1], qh4, &kh4[2]);
                mma16816(s[2 * np + 1], qh4, &kl4[2]);
                mma16816(s[2 * np + 1], ql4, &kh4[2]);
            }
        }

        // ---- online softmax (log2 domain; Q pre-scaled by 0.125*log2e)
        float rmaxA = -1e30f, rmaxB = -1e30f;
#pragma unroll
        for (int nt = 0; nt < 8; nt++) {
            rmaxA = fmaxf(rmaxA, fmaxf(s[nt][0], s[nt][1]));
            rmaxB = fmaxf(rmaxB, fmaxf(s[nt][2], s[nt][3]));
        }
        rmaxA = fmaxf(rmaxA, __shfl_xor_sync(0xffffffffu, rmaxA, 1));
        rmaxA = fmaxf(rmaxA, __shfl_xor_sync(0xffffffffu, rmaxA, 2));
        rmaxB = fmaxf(rmaxB, __shfl_xor_sync(0xffffffffu, rmaxB, 1));
        rmaxB = fmaxf(rmaxB, __shfl_xor_sync(0xffffffffu, rmaxB, 2));

        float mnA = fmaxf(mA, rmaxA), mnB = fmaxf(mB, rmaxB);
        float corrA = exp2f(mA - mnA), corrB = exp2f(mB - mnB);
        mA = mnA; mB = mnB;

        float rsA = 0.f, rsB = 0.f;
#pragma unroll
        for (int nt = 0; nt < 8; nt++) {
            s[nt][0] = exp2f(s[nt][0] - mnA);
            s[nt][1] = exp2f(s[nt][1] - mnA);
            s[nt][2] = exp2f(s[nt][2] - mnB);
            s[nt][3] = exp2f(s[nt][3] - mnB);
            rsA += s[nt][0] + s[nt][1];
            rsB += s[nt][2] + s[nt][3];
        }
        rsA += __shfl_xor_sync(0xffffffffu, rsA, 1);
        rsA += __shfl_xor_sync(0xffffffffu, rsA, 2);
        rsB += __shfl_xor_sync(0xffffffffu, rsB, 1);
        rsB += __shfl_xor_sync(0xffffffffu, rsB, 2);
        lA = lA * corrA + rsA;
        lB = lB * corrB + rsB;
#pragma unroll
        for (int nt = 0; nt < 8; nt++) {
            o[nt][0] *= corrA; o[nt][1] *= corrA;
            o[nt][2] *= corrB; o[nt][3] *= corrB;
        }

        // ---- O += P V (P hi/lo from registers, V per-np via ldmatrix.trans)
#pragma unroll
        for (int t4 = 0; t4 < 4; t4++) {
            uint32_t ph[4], pl[4];
            {
                const float* s0 = s[2 * t4];
                const float* s1 = s[2 * t4 + 1];
                pk_hilo2(s0[0], s0[1], ph[0], pl[0]);
                pk_hilo2(s0[2], s0[3], ph[1], pl[1]);
                pk_hilo2(s1[0], s1[1], ph[2], pl[2]);
                pk_hilo2(s1[2], s1[3], ph[3], pl[3]);
            }
            const int vRow = t4 * 16 + (lane & 15);
#pragma unroll
            for (int np = 0; np < 4; np++) {
                uint32_t vh[4], vl[4];
                uint32_t off = aswz(vRow, np * 2 + (lane >> 4));
                ldm4t(vh, sVh + off);
                ldm4t(vl, sVl + off);
                mma16816(o[2 * np],     ph, &vh[0]);
                mma16816(o[2 * np],     ph, &vl[0]);
                mma16816(o[2 * np],     pl, &vh[0]);
                mma16816(o[2 * np + 1], ph, &vh[2]);
                mma16816(o[2 * np + 1], ph, &vl[2]);
                mma16816(o[2 * np + 1], pl, &vh[2]);
            }
        }
    }

    // ---- epilogue: normalize, split hi/lo, store ctx
    const float ivA = 1.f / lA, ivB = 1.f / lB;
    const size_t tokA = row0 + q0 + wid * 16 + (lane >> 2);
    const size_t tokB = tokA + 8;
#pragma unroll
    for (int nt = 0; nt < 8; nt++) {
        const int col = h * 64 + nt * 8 + (lane & 3) * 2;
        uint32_t h0, l0, h1, l1;
        pk_hilo2(o[nt][0] * ivA, o[nt][1] * ivA, h0, l0);
        pk_hilo2(o[nt][2] * ivB, o[nt][3] * ivB, h1, l1);
        *(uint32_t*)(chi + tokA * D_MODEL + col) = h0;
        *(uint32_t*)(clo + tokA * D_MODEL + col) = l0;
        *(uint32_t*)(chi + tokB * D_MODEL + col) = h1;
        *(uint32_t*)(clo + tokB * D_MODEL + col) = l1;
    }
}

// ---------------------------------------------------------------------------
// Launch
// ---------------------------------------------------------------------------
extern "C" void kernel_launch(void* const* d_in, const int* in_sizes, int n_in,
                              void* d_out, int out_size)
{
    const float* x      = (const float*)d_in[0];
    const float* w_qkv  = (const float*)d_in[1];
    const float* b_qkv  = (const float*)d_in[2];
    const float* w_proj = (const float*)d_in[3];
    const float* b_proj = (const float*)d_in[4];
    float* out = (float*)d_out;

    __nv_bfloat16 *xhi, *xlo, *qkvhi, *qkvlo, *chi, *clo, *wqhi, *wqlo, *wphi, *wplo;
    cudaGetSymbolAddress((void**)&xhi, g_xhi);
    cudaGetSymbolAddress((void**)&xlo, g_xlo);
    cudaGetSymbolAddress((void**)&qkvhi, g_qkvhi);
    cudaGetSymbolAddress((void**)&qkvlo, g_qkvlo);
    cudaGetSymbolAddress((void**)&chi, g_chi);
    cudaGetSymbolAddress((void**)&clo, g_clo);
    cudaGetSymbolAddress((void**)&wqhi, g_wqhi);
    cudaGetSymbolAddress((void**)&wqlo, g_wqlo);
    cudaGetSymbolAddress((void**)&wphi, g_wphi);
    cudaGetSymbolAddress((void**)&wplo, g_wplo);

    cudaFuncSetAttribute(gemm_mma_bf16x3,
                         cudaFuncAttributeMaxDynamicSharedMemorySize, GEMM_SMEM);
    cudaFuncSetAttribute(attn_mma,
                         cudaFuncAttributeMaxDynamicSharedMemorySize, ATT_SMEM);

    // 1) x -> bf16 hi/lo; weights transpose+split
    {
        int n4 = NTOK * D_MODEL / 4;
        convert_hilo<<<(n4 + 255) / 256, 256>>>((const float4*)x, (uint2*)xhi, (uint2*)xlo, n4);
        dim3 tg(3 * D_MODEL / 32, D_MODEL / 32);
        transpose_hilo<<<tg, dim3(32, 8)>>>(w_qkv, D_MODEL, 3 * D_MODEL, wqhi, wqlo);
        dim3 tp(D_MODEL / 32, D_MODEL / 32);
        transpose_hilo<<<tp, dim3(32, 8)>>>(w_proj, D_MODEL, D_MODEL, wphi, wplo);
    }

    // 2) QKV GEMM -> bf16 hi/lo qkv (Q block pre-scaled by QSCALE)
    {
        dim3 grid(3 * D_MODEL / 128, NTOK / 128);
        gemm_mma_bf16x3<<<grid, 256, GEMM_SMEM>>>(NTOK, 3 * D_MODEL, D_MODEL,
                                                  xhi, xlo, wqhi, wqlo, b_qkv,
                                                  nullptr, qkvhi, qkvlo, 1);
    }

    // 3) HMMA flash attention -> bf16 hi/lo ctx
    {
        dim3 grid(SEQ / 128, BATCH * HEADS);
        attn_mma<<<grid, 256, ATT_SMEM>>>(qkvhi, qkvlo, chi, clo);
    }

    // 4) Proj GEMM -> fp32 out
    {
        dim3 grid(D_MODEL / 128, NTOK / 128);
        gemm_mma_bf16x3<<<grid, 256, GEMM_SMEM>>>(NTOK, D_MODEL, D_MODEL,
                                                  chi, clo, wphi, wplo, b_proj,
                                                  out, nullptr, nullptr, 0);
    }
}

// round 10
// speedup vs baseline: 1.4496x; 1.3889x over previous
#include <cuda_runtime.h>
#include <cuda_fp16.h>
#include <cstdint>

#define D_MODEL 1024
#define HEADS   16
#define DH      64
#define BATCH   4
#define SEQ     2048
#define NTOK    (BATCH * SEQ)   // 8192

// Q pre-scale: 0.125 (dh^-1/2) * log2(e)  -> softmax done in base-2 domain
#define QSCALE 0.1803368801111204f

// ---------------- scratch (device globals; no runtime alloc allowed) -------
// fp16 hi/lo split: lo kept ONLY for left-hand GEMM operands (x, qkv-Q, ctx, P)
__device__ __half g_xhi[(size_t)NTOK * D_MODEL];
__device__ __half g_xlo[(size_t)NTOK * D_MODEL];
__device__ __half g_qkvhi[(size_t)NTOK * 3 * D_MODEL]; // [8192,3072]
__device__ __half g_qkvlo[(size_t)NTOK * 3 * D_MODEL]; // only Q cols consumed
__device__ __half g_chi[(size_t)NTOK * D_MODEL];
__device__ __half g_clo[(size_t)NTOK * D_MODEL];
__device__ __half g_wqhi[(size_t)3 * D_MODEL * D_MODEL]; // Wqkv^T [3072,1024], hi only
__device__ __half g_wphi[(size_t)D_MODEL * D_MODEL];     // Wproj^T, hi only

// ---------------------------------------------------------------------------
// Helpers (portable ISA only — .target sm_103 without 'a')
// ---------------------------------------------------------------------------
__device__ __forceinline__ uint32_t smem_u32(const void* p) {
    uint32_t a;
    asm("{ .reg .u64 t; cvta.to.shared.u64 t, %1; cvt.u32.u64 %0, t; }"
        : "=r"(a) : "l"(p));
    return a;
}
__device__ __forceinline__ void cp16(uint32_t saddr, const void* gaddr) {
    asm volatile("cp.async.cg.shared.global [%0], [%1], 16;"
        :: "r"(saddr), "l"(gaddr));
}
#define CP_COMMIT() asm volatile("cp.async.commit_group;")
#define CP_WAIT(n)  asm volatile("cp.async.wait_group %0;" :: "n"(n))

__device__ __forceinline__ void ldm4(uint32_t* r, uint32_t a) {
    asm volatile("ldmatrix.sync.aligned.m8n8.x4.shared.b16 {%0,%1,%2,%3}, [%4];"
        : "=r"(r[0]), "=r"(r[1]), "=r"(r[2]), "=r"(r[3]) : "r"(a));
}
__device__ __forceinline__ void ldm4t(uint32_t* r, uint32_t a) {
    asm volatile("ldmatrix.sync.aligned.m8n8.x4.trans.shared.b16 {%0,%1,%2,%3}, [%4];"
        : "=r"(r[0]), "=r"(r[1]), "=r"(r[2]), "=r"(r[3]) : "r"(a));
}
__device__ __forceinline__ void mma16816(float* c, const uint32_t* a, const uint32_t* b) {
    asm volatile(
        "mma.sync.aligned.m16n8k16.row.col.f32.f16.f16.f32 "
        "{%0,%1,%2,%3}, {%4,%5,%6,%7}, {%8,%9}, {%0,%1,%2,%3};"
        : "+f"(c[0]), "+f"(c[1]), "+f"(c[2]), "+f"(c[3])
        : "r"(a[0]), "r"(a[1]), "r"(a[2]), "r"(a[3]), "r"(b[0]), "r"(b[1]));
}

// fp16 hi/lo pack: h = half2(a,b); l = residuals as half2
__device__ __forceinline__ void pk_hilo2(float a, float b, uint32_t& h, uint32_t& l) {
    __half2 hh = __floats2half2_rn(a, b);
    h = *reinterpret_cast<uint32_t*>(&hh);
    float ha = __half2float(__low2half(hh));
    float hb = __half2float(__high2half(hh));
    __half2 ll = __floats2half2_rn(a - ha, b - hb);
    l = *reinterpret_cast<uint32_t*>(&ll);
}
__device__ __forceinline__ uint32_t pk_hi2(float a, float b) {
    __half2 hh = __floats2half2_rn(a, b);
    return *reinterpret_cast<uint32_t*>(&hh);
}

// swizzled offset in a 32-col f16 tile (64B rows, 4 chunks)
__device__ __forceinline__ uint32_t gswz(int row, int chunk) {
    return (uint32_t)row * 64 + ((chunk ^ ((row >> 1) & 3)) << 4);
}
// swizzled offset in a 64-col f16 tile (128B rows, 8 chunks)
__device__ __forceinline__ uint32_t aswz(int row, int chunk) {
    return (uint32_t)row * 128 + ((chunk ^ (row & 7)) << 4);
}

// ---------------------------------------------------------------------------
// Conversion kernels
// ---------------------------------------------------------------------------
__global__ __launch_bounds__(256) void convert_hilo(
    const float4* __restrict__ in, uint2* __restrict__ hi, uint2* __restrict__ lo, int n4)
{
    int i = blockIdx.x * 256 + threadIdx.x;
    if (i >= n4) return;
    float4 v = in[i];
    uint2 h, l;
    pk_hilo2(v.x, v.y, h.x, l.x);
    pk_hilo2(v.z, v.w, h.y, l.y);
    hi[i] = h;
    lo[i] = l;
}

// W [K,N] fp32 row-major -> T [N,K] fp16 hi only (transpose + round)
__global__ __launch_bounds__(256) void transpose_hi(
    const float* __restrict__ W, int K, int N, __half* __restrict__ Thi)
{
    __shared__ float tile[32][33];
    int kb = blockIdx.y * 32, nb = blockIdx.x * 32;
    int tx = threadIdx.x, ty = threadIdx.y;
#pragma unroll
    for (int i = 0; i < 32; i += 8)
        tile[ty + i][tx] = W[(size_t)(kb + ty + i) * N + nb + tx];
    __syncthreads();
#pragma unroll
    for (int i = 0; i < 32; i += 8) {
        int n = nb + ty + i, k = kb + tx;
        Thi[(size_t)n * K + k] = __float2half_rn(tile[tx][ty + i]);
    }
}

// ---------------------------------------------------------------------------
// HMMA fp16x2 GEMM: C = (Ahi+Alo)[M,K] @ Bhi[N,K]^T + bias
// 128x128 CTA tile, K-chunk 32, swizzled 64B rows, 4-stage, 1 sync/iter.
// hilo_out=1 additionally pre-scales columns < 1024 (the Q block) by QSCALE.
// ---------------------------------------------------------------------------
#define TILEB    8192
#define STAGEB   (3 * TILEB)   // Ahi, Alo, Bhi = 24576
#define NSTAGE   4
#define GEMM_SMEM (NSTAGE * STAGEB)  // 98304

__global__ __launch_bounds__(256, 2) void gemm_mma_f16x2(
    int M, int N, int K,
    const __half* __restrict__ Ahi, const __half* __restrict__ Alo,
    const __half* __restrict__ Bhi,
    const float* __restrict__ bias,
    float* __restrict__ C,
    __half* __restrict__ Chi, __half* __restrict__ Clo,
    int hilo_out)
{
    extern __shared__ char smem[];
    const uint32_t sb = smem_u32(smem);

    const int tid = threadIdx.x;
    const int lane = tid & 31;
    const int wid = tid >> 5;
    const int warpM = wid & 3;
    const int warpN = wid >> 2;

    const size_t arow0 = (size_t)blockIdx.y * 128 * K;
    const size_t brow0 = (size_t)blockIdx.x * 128 * K;

    const int ldRow = tid >> 2;
    const int ldCh  = tid & 3;

    float acc[2][8][4] = {};
    const int NCH = K / 32;

    auto issue = [&](int c, int s) {
        const int k0 = c * 32;
        const uint32_t st = sb + s * STAGEB;
#pragma unroll
        for (int p = 0; p < 2; p++) {
            const int row = ldRow + p * 64;
            const uint32_t soff = gswz(row, ldCh);
            const size_t goff = (size_t)row * K + k0 + ldCh * 8;
            cp16(st + 0 * TILEB + soff, Ahi + arow0 + goff);
            cp16(st + 1 * TILEB + soff, Alo + arow0 + goff);
            cp16(st + 2 * TILEB + soff, Bhi + brow0 + goff);
        }
    };

    issue(0, 0); CP_COMMIT();
    issue(1, 1); CP_COMMIT();
    issue(2, 2); CP_COMMIT();

    for (int c = 0; c < NCH; c++) {
        if (c + 2 < NCH) CP_WAIT(2);
        else if (c + 1 < NCH) CP_WAIT(1);
        else CP_WAIT(0);
        __syncthreads();
        if (c + 3 < NCH) { issue(c + 3, (c + 3) % NSTAGE); CP_COMMIT(); }

        const uint32_t st  = sb + (c % NSTAGE) * STAGEB;
        const uint32_t sAh = st;
        const uint32_t sAl = st + TILEB;
        const uint32_t sBh = st + 2 * TILEB;

#pragma unroll
        for (int ks = 0; ks < 2; ks++) {
            uint32_t ahi[2][4], alo[2][4];
            const int aRow = warpM * 32 + (lane & 15);
            const int aCh  = ks * 2 + (lane >> 4);
#pragma unroll
            for (int mt = 0; mt < 2; mt++) {
                const uint32_t off = gswz(aRow + mt * 16, aCh);
                ldm4(ahi[mt], sAh + off);
                ldm4(alo[mt], sAl + off);
            }
            uint32_t bhi[4][4];
            const int bRow = warpN * 64 + ((lane >> 4) << 3) + (lane & 7);
            const int bCh  = ks * 2 + ((lane >> 3) & 1);
#pragma unroll
            for (int ntp = 0; ntp < 4; ntp++) {
                const uint32_t off = gswz(bRow + ntp * 16, bCh);
                ldm4(bhi[ntp], sBh + off);
            }
#pragma unroll
            for (int mt = 0; mt < 2; mt++) {
#pragma unroll
                for (int nt = 0; nt < 8; nt++) {
                    const uint32_t* bh = &bhi[nt >> 1][(nt & 1) * 2];
                    mma16816(acc[mt][nt], ahi[mt], bh);
                    mma16816(acc[mt][nt], alo[mt], bh);
                }
            }
        }
    }

    const int rBase = blockIdx.y * 128 + warpM * 32 + (lane >> 2);
    const int cBase = blockIdx.x * 128 + warpN * 64 + (lane & 3) * 2;
#pragma unroll
    for (int mt = 0; mt < 2; mt++) {
#pragma unroll
        for (int nt = 0; nt < 8; nt++) {
            const int gc = cBase + nt * 8;
            const float b0 = bias[gc], b1 = bias[gc + 1];
            const int r0 = rBase + mt * 16;
            float v00 = acc[mt][nt][0] + b0, v01 = acc[mt][nt][1] + b1;
            float v10 = acc[mt][nt][2] + b0, v11 = acc[mt][nt][3] + b1;
            if (!hilo_out) {
                *(float2*)(C + (size_t)r0 * N + gc) = make_float2(v00, v01);
                *(float2*)(C + (size_t)(r0 + 8) * N + gc) = make_float2(v10, v11);
            } else {
                // Q block (cols < 1024) pre-scaled for log2-domain softmax
                const float qs = (gc < 1024) ? QSCALE : 1.0f;
                v00 *= qs; v01 *= qs; v10 *= qs; v11 *= qs;
                uint32_t h0, l0, h1, l1;
                pk_hilo2(v00, v01, h0, l0);
                pk_hilo2(v10, v11, h1, l1);
                *(uint32_t*)(Chi + (size_t)r0 * N + gc) = h0;
                *(uint32_t*)(Clo + (size_t)r0 * N + gc) = l0;
                *(uint32_t*)(Chi + (size_t)(r0 + 8) * N + gc) = h1;
                *(uint32_t*)(Clo + (size_t)(r0 + 8) * N + gc) = l1;
            }
        }
    }
}

// ---------------------------------------------------------------------------
// HMMA flash attention (fp16x2, log2-domain softmax).
// Q (hi+lo) staged in smem; KV = K-hi + V-hi only, 4-stage pipeline.
// 98304B smem, 2 CTAs/SM. CTA: 128 queries of one (b,h); 8 warps x 16 rows.
// ---------------------------------------------------------------------------
#define AQTILE   16384
#define AKVT     8192
#define ASTAGEB  (2 * AKVT)              // Kh, Vh = 16384
#define ANST     4
#define ATT_SMEM (2 * AQTILE + ANST * ASTAGEB)  // 98304

__global__ __launch_bounds__(256, 2) void attn_mma(
    const __half* __restrict__ qkvhi,
    const __half* __restrict__ qkvlo,
    __half* __restrict__ chi,
    __half* __restrict__ clo)
{
    extern __shared__ char smem[];
    const uint32_t sb = smem_u32(smem);
    const uint32_t sQh = sb;
    const uint32_t sQl = sb + AQTILE;
    const uint32_t sKV = sb + 2 * AQTILE;

    const int tid = threadIdx.x;
    const int lane = tid & 31;
    const int wid = tid >> 5;

    const int b = blockIdx.y >> 4;
    const int h = blockIdx.y & 15;
    const int q0 = blockIdx.x * 128;
    const size_t row0 = (size_t)b * SEQ;

    const size_t qoff = (row0 + q0) * 3072 + h * 64;
    const size_t koff = row0 * 3072 + 1024 + h * 64;
    const size_t voff = row0 * 3072 + 2048 + h * 64;

#pragma unroll
    for (int i = 0; i < 4; i++) {
        int idx = tid + i * 256;
        int row = idx >> 3, ch = idx & 7;
        uint32_t so = aswz(row, ch);
        size_t go = (size_t)row * 3072 + ch * 8;
        cp16(sQh + so, qkvhi + qoff + go);
        cp16(sQl + so, qkvlo + qoff + go);
    }

    auto issueKV = [&](int t, int s) {
        const uint32_t st = sKV + s * ASTAGEB;
        const size_t kvrow = (size_t)t * 64;
#pragma unroll
        for (int i = 0; i < 2; i++) {
            int idx = tid + i * 256;
            int row = idx >> 3, ch = idx & 7;
            uint32_t so = aswz(row, ch);
            size_t go = (kvrow + row) * 3072 + ch * 8;
            cp16(st + 0 * AKVT + so, qkvhi + koff + go);
            cp16(st + 1 * AKVT + so, qkvhi + voff + go);
        }
    };
    issueKV(0, 0); CP_COMMIT();
    issueKV(1, 1); CP_COMMIT();
    issueKV(2, 2); CP_COMMIT();

    float o[8][4] = {};
    float mA = -1e30f, mB = -1e30f, lA = 0.f, lB = 0.f;

    const int bRow0 = ((lane >> 4) << 3) + (lane & 7);
    const int bChSel = (lane >> 3) & 1;

    const int NT = SEQ / 64;
    for (int t = 0; t < NT; t++) {
        if (t + 2 < NT) CP_WAIT(2);
        else if (t + 1 < NT) CP_WAIT(1);
        else CP_WAIT(0);
        __syncthreads();
        if (t + 3 < NT) { issueKV(t + 3, (t + 3) % ANST); CP_COMMIT(); }

        const uint32_t st  = sKV + (t % ANST) * ASTAGEB;
        const uint32_t sKh = st;
        const uint32_t sVh = st + AKVT;

        // ---- S = Q K^T (fp16x2: (qh+ql) @ kh)
        float s[8][4] = {};
        const int aRow = wid * 16 + (lane & 15);
#pragma unroll
        for (int ks = 0; ks < 4; ks++) {
            uint32_t qh4[4], ql4[4];
            {
                uint32_t off = aswz(aRow, ks * 2 + (lane >> 4));
                ldm4(qh4, sQh + off);
                ldm4(ql4, sQl + off);
            }
#pragma unroll
            for (int np = 0; np < 4; np++) {
                uint32_t kh4[4];
                uint32_t off = aswz(bRow0 + np * 16, ks * 2 + bChSel);
                ldm4(kh4, sKh + off);
                mma16816(s[2 * np],     qh4, &kh4[0]);
                mma16816(s[2 * np],     ql4, &kh4[0]);
                mma16816(s[2 * np + 1], qh4, &kh4[2]);
                mma16816(s[2 * np + 1], ql4, &kh4[2]);
            }
        }

        // ---- online softmax (log2 domain; Q pre-scaled by 0.125*log2e)
        float rmaxA = -1e30f, rmaxB = -1e30f;
#pragma unroll
        for (int nt = 0; nt < 8; nt++) {
            rmaxA = fmaxf(rmaxA, fmaxf(s[nt][0], s[nt][1]));
            rmaxB = fmaxf(rmaxB, fmaxf(s[nt][2], s[nt][3]));
        }
        rmaxA = fmaxf(rmaxA, __shfl_xor_sync(0xffffffffu, rmaxA, 1));
        rmaxA = fmaxf(rmaxA, __shfl_xor_sync(0xffffffffu, rmaxA, 2));
        rmaxB = fmaxf(rmaxB, __shfl_xor_sync(0xffffffffu, rmaxB, 1));
        rmaxB = fmaxf(rmaxB, __shfl_xor_sync(0xffffffffu, rmaxB, 2));

        float mnA = fmaxf(mA, rmaxA), mnB = fmaxf(mB, rmaxB);
        float corrA = exp2f(mA - mnA), corrB = exp2f(mB - mnB);
        mA = mnA; mB = mnB;

        float rsA = 0.f, rsB = 0.f;
#pragma unroll
        for (int nt = 0; nt < 8; nt++) {
            s[nt][0] = exp2f(s[nt][0] - mnA);
            s[nt][1] = exp2f(s[nt][1] - mnA);
            s[nt][2] = exp2f(s[nt][2] - mnB);
            s[nt][3] = exp2f(s[nt][3] - mnB);
            rsA += s[nt][0] + s[nt][1];
            rsB += s[nt][2] + s[nt][3];
        }
        rsA += __shfl_xor_sync(0xffffffffu, rsA, 1);
        rsA += __shfl_xor_sync(0xffffffffu, rsA, 2);
        rsB += __shfl_xor_sync(0xffffffffu, rsB, 1);
        rsB += __shfl_xor_sync(0xffffffffu, rsB, 2);
        lA = lA * corrA + rsA;
        lB = lB * corrB + rsB;
#pragma unroll
        for (int nt = 0; nt < 8; nt++) {
            o[nt][0] *= corrA; o[nt][1] *= corrA;
            o[nt][2] *= corrB; o[nt][3] *= corrB;
        }

        // ---- O += P V  (fp16x2: (ph+pl) @ vh, V via ldmatrix.trans)
#pragma unroll
        for (int t4 = 0; t4 < 4; t4++) {
            uint32_t ph[4], pl[4];
            {
                const float* s0 = s[2 * t4];
                const float* s1 = s[2 * t4 + 1];
                pk_hilo2(s0[0], s0[1], ph[0], pl[0]);
                pk_hilo2(s0[2], s0[3], ph[1], pl[1]);
                pk_hilo2(s1[0], s1[1], ph[2], pl[2]);
                pk_hilo2(s1[2], s1[3], ph[3], pl[3]);
            }
            const int vRow = t4 * 16 + (lane & 15);
#pragma unroll
            for (int np = 0; np < 4; np++) {
                uint32_t vh[4];
                uint32_t off = aswz(vRow, np * 2 + (lane >> 4));
                ldm4t(vh, sVh + off);
                mma16816(o[2 * np],     ph, &vh[0]);
                mma16816(o[2 * np],     pl, &vh[0]);
                mma16816(o[2 * np + 1], ph, &vh[2]);
                mma16816(o[2 * np + 1], pl, &vh[2]);
            }
        }
    }

    // ---- epilogue: normalize, split hi/lo, store ctx
    const float ivA = 1.f / lA, ivB = 1.f / lB;
    const size_t tokA = row0 + q0 + wid * 16 + (lane >> 2);
    const size_t tokB = tokA + 8;
#pragma unroll
    for (int nt = 0; nt < 8; nt++) {
        const int col = h * 64 + nt * 8 + (lane & 3) * 2;
        uint32_t h0, l0, h1, l1;
        pk_hilo2(o[nt][0] * ivA, o[nt][1] * ivA, h0, l0);
        pk_hilo2(o[nt][2] * ivB, o[nt][3] * ivB, h1, l1);
        *(uint32_t*)(chi + tokA * D_MODEL + col) = h0;
        *(uint32_t*)(clo + tokA * D_MODEL + col) = l0;
        *(uint32_t*)(chi + tokB * D_MODEL + col) = h1;
        *(uint32_t*)(clo + tokB * D_MODEL + col) = l1;
    }
}

// ---------------------------------------------------------------------------
// Launch
// ---------------------------------------------------------------------------
extern "C" void kernel_launch(void* const* d_in, const int* in_sizes, int n_in,
                              void* d_out, int out_size)
{
    const float* x      = (const float*)d_in[0];
    const float* w_qkv  = (const float*)d_in[1];
    const float* b_qkv  = (const float*)d_in[2];
    const float* w_proj = (const float*)d_in[3];
    const float* b_proj = (const float*)d_in[4];
    float* out = (float*)d_out;

    __half *xhi, *xlo, *qkvhi, *qkvlo, *chi, *clo, *wqhi, *wphi;
    cudaGetSymbolAddress((void**)&xhi, g_xhi);
    cudaGetSymbolAddress((void**)&xlo, g_xlo);
    cudaGetSymbolAddress((void**)&qkvhi, g_qkvhi);
    cudaGetSymbolAddress((void**)&qkvlo, g_qkvlo);
    cudaGetSymbolAddress((void**)&chi, g_chi);
    cudaGetSymbolAddress((void**)&clo, g_clo);
    cudaGetSymbolAddress((void**)&wqhi, g_wqhi);
    cudaGetSymbolAddress((void**)&wphi, g_wphi);

    cudaFuncSetAttribute(gemm_mma_f16x2,
                         cudaFuncAttributeMaxDynamicSharedMemorySize, GEMM_SMEM);
    cudaFuncSetAttribute(attn_mma,
                         cudaFuncAttributeMaxDynamicSharedMemorySize, ATT_SMEM);

    // 1) x -> fp16 hi/lo; weights transpose (hi only)
    {
        int n4 = NTOK * D_MODEL / 4;
        convert_hilo<<<(n4 + 255) / 256, 256>>>((const float4*)x, (uint2*)xhi, (uint2*)xlo, n4);
        dim3 tg(3 * D_MODEL / 32, D_MODEL / 32);
        transpose_hi<<<tg, dim3(32, 8)>>>(w_qkv, D_MODEL, 3 * D_MODEL, wqhi);
        dim3 tp(D_MODEL / 32, D_MODEL / 32);
        transpose_hi<<<tp, dim3(32, 8)>>>(w_proj, D_MODEL, D_MODEL, wphi);
    }

    // 2) QKV GEMM -> fp16 hi/lo qkv (Q block pre-scaled by QSCALE)
    {
        dim3 grid(3 * D_MODEL / 128, NTOK / 128);
        gemm_mma_f16x2<<<grid, 256, GEMM_SMEM>>>(NTOK, 3 * D_MODEL, D_MODEL,
                                                 xhi, xlo, wqhi, b_qkv,
                                                 nullptr, qkvhi, qkvlo, 1);
    }

    // 3) HMMA flash attention -> fp16 hi/lo ctx
    {
        dim3 grid(SEQ / 128, BATCH * HEADS);
        attn_mma<<<grid, 256, ATT_SMEM>>>(qkvhi, qkvlo, chi, clo);
    }

    // 4) Proj GEMM -> fp32 out
    {
        dim3 grid(D_MODEL / 128, NTOK / 128);
        gemm_mma_f16x2<<<grid, 256, GEMM_SMEM>>>(NTOK, D_MODEL, D_MODEL,
                                                 chi, clo, wphi, b_proj,
                                                 out, nullptr, nullptr, 0);
    }
}